// round 8
// baseline (speedup 1.0000x reference)
#include <cuda_runtime.h>
#include <math.h>

#define NB  8
#define H   12
#define DH  64
#define LV  1568
#define LA  512
#define NCV 392
#define NCA 256
#define ROW 5696
#define OFF_PROBV 0
#define OFF_PROBA 1568
#define OFF_VCLS  2080
#define OFF_ACLS  2848
#define OFF_PRAV  3616
#define OFF_PRVA  5184

// ---------- scratch ----------
__device__ int   g_cidx_v[NB * NCV];   // sorted gathered v-token ids
__device__ float g_w_v[NB * NCV];
__device__ int   g_cidx_a[NB * NCA];
__device__ float g_w_a[NB * NCA];
__device__ float g_invS_av[NB];
__device__ float g_invS_va[NB];
__device__ float g_probv[NB * NCV];
__device__ float g_proba[NB * NCA];
__device__ float g_posv[NB * H * LV];  // pos numerators over ALL v columns
__device__ float g_posa[NB * H * LA];

// ---------- kernel 1: sorted gather via inverse permutation + block scan ----------
// grid (NB, 2): side 0 = v, side 1 = a
__global__ void kprep(const float* __restrict__ n_attn_av,
                      const float* __restrict__ n_attn_va,
                      const int* __restrict__ ids_v,
                      const int* __restrict__ ids_a) {
    int n = blockIdx.x, side = blockIdx.y, tid = threadIdx.x;
    int lane = tid & 31, wrp = tid >> 5;
    __shared__ int   s_rank[LV];
    __shared__ int   s_wsum[16];
    __shared__ float s_red[512];

    int full = side ? LA : LV;
    int cnt  = side ? NCA : NCV;
    const int*   ids = side ? ids_a : ids_v;
    const float* na  = side ? n_attn_va : n_attn_av;

    // inverse permutation: rank of token j within ids
    for (int t = tid; t < full; t += 512) s_rank[ids[n * full + t]] = t;
    // zero the v-side pos accumulator (atomicAdd targets in kpos)
    if (side == 0)
        for (int t = tid; t < H * LV; t += 512) g_posv[n * H * LV + t] = 0.f;
    // zero prob accumulators
    if (side) { if (tid < NCA) g_proba[n * NCA + tid] = 0.f; }
    else      { if (tid < NCV) g_probv[n * NCV + tid] = 0.f; }
    __syncthreads();

    // blocked flags: token j kept iff rank < cnt; sorted order == ascending j
    int per = (full + 511) >> 9;      // 4 for LV, 1 for LA
    int base = tid * per;
    int keep[4]; int k = 0; float ws = 0.f;
    for (int i = 0; i < per; i++) {
        int j = base + i;
        if (j < full && s_rank[j] < cnt) { keep[k++] = j; ws += na[n * full + j]; }
    }
    // block exclusive scan of per-thread counts
    int inc = k;
    for (int d = 1; d < 32; d <<= 1) {
        int v = __shfl_up_sync(0xffffffffu, inc, d);
        if (lane >= d) inc += v;
    }
    if (lane == 31) s_wsum[wrp] = inc;
    __syncthreads();
    if (wrp == 0 && lane < 16) {
        int v = s_wsum[lane];
        for (int d = 1; d < 16; d <<= 1) {
            int u = __shfl_up_sync(0xffffu, v, d);
            if (lane >= d) v += u;
        }
        s_wsum[lane] = v;
    }
    __syncthreads();
    int off = (wrp ? s_wsum[wrp - 1] : 0) + inc - k;
    for (int i = 0; i < k; i++) {
        int j = keep[i];
        int slot = off + i;
        if (side) { g_cidx_a[n * NCA + slot] = j; g_w_a[n * NCA + slot] = na[n * LA + j]; }
        else      { g_cidx_v[n * NCV + slot] = j; g_w_v[n * NCV + slot] = na[n * LV + j]; }
    }
    // weight-sum reduction
    s_red[tid] = ws;
    __syncthreads();
    for (int s = 256; s > 0; s >>= 1) {
        if (tid < s) s_red[tid] += s_red[tid + s];
        __syncthreads();
    }
    if (tid == 0) {
        if (side) g_invS_va[n] = 1.f / s_red[0];
        else      g_invS_av[n] = 1.f / s_red[0];
    }
}

// ---------- kernel 2: pos numerators, full-row coalesced streaming ----------
// grid (H, NB, 3): z=0/1 -> v side, a-row chunks [0:128)/[128:256); z=2 -> a side, all 392 v rows
__global__ void __launch_bounds__(512, 2)
kpos(const float* __restrict__ M_av, const float* __restrict__ M_va) {
    int h = blockIdx.x, n = blockIdx.y, z = blockIdx.z;
    int tid = threadIdx.x;
    __shared__ int   s_off[NCV];
    __shared__ float s_w[NCV];

    if (z < 2) {
        // v side: weighted sum of gathered a-rows of M_av over ALL 1568 columns
        for (int a = tid; a < NCA; a += 512) {
            s_off[a] = g_cidx_a[n * NCA + a] * LV;
            s_w[a]   = g_w_a[n * NCA + a];
        }
        __syncthreads();
        const float* Mb = M_av + (size_t)(n * H + h) * LA * LV;
        int r0 = z * 128;
        if (tid < LV / 4) {   // 392 float4 slots cover the full row
            float4 acc0 = {0.f, 0.f, 0.f, 0.f}, acc1 = {0.f, 0.f, 0.f, 0.f};
            #pragma unroll 1
            for (int r = r0; r < r0 + 128; r += 4) {
                float4 m0 = ((const float4*)(Mb + s_off[r + 0]))[tid];
                float4 m1 = ((const float4*)(Mb + s_off[r + 1]))[tid];
                float4 m2 = ((const float4*)(Mb + s_off[r + 2]))[tid];
                float4 m3 = ((const float4*)(Mb + s_off[r + 3]))[tid];
                float w0 = s_w[r + 0], w1 = s_w[r + 1], w2 = s_w[r + 2], w3 = s_w[r + 3];
                acc0.x = fmaf(m0.x, w0, acc0.x); acc0.y = fmaf(m0.y, w0, acc0.y);
                acc0.z = fmaf(m0.z, w0, acc0.z); acc0.w = fmaf(m0.w, w0, acc0.w);
                acc1.x = fmaf(m1.x, w1, acc1.x); acc1.y = fmaf(m1.y, w1, acc1.y);
                acc1.z = fmaf(m1.z, w1, acc1.z); acc1.w = fmaf(m1.w, w1, acc1.w);
                acc0.x = fmaf(m2.x, w2, acc0.x); acc0.y = fmaf(m2.y, w2, acc0.y);
                acc0.z = fmaf(m2.z, w2, acc0.z); acc0.w = fmaf(m2.w, w2, acc0.w);
                acc1.x = fmaf(m3.x, w3, acc1.x); acc1.y = fmaf(m3.y, w3, acc1.y);
                acc1.z = fmaf(m3.z, w3, acc1.z); acc1.w = fmaf(m3.w, w3, acc1.w);
            }
            float* dst = &g_posv[(size_t)(n * H + h) * LV + 4 * tid];
            atomicAdd(dst + 0, acc0.x + acc1.x);
            atomicAdd(dst + 1, acc0.y + acc1.y);
            atomicAdd(dst + 2, acc0.z + acc1.z);
            atomicAdd(dst + 3, acc0.w + acc1.w);
        }
    } else {
        // a side: weighted sum of gathered v-rows of M_va over all 512 columns (sole writer)
        for (int a = tid; a < NCV; a += 512) {
            s_off[a] = g_cidx_v[n * NCV + a] * LA;
            s_w[a]   = g_w_v[n * NCV + a];
        }
        __syncthreads();
        const float* Mb = M_va + (size_t)(n * H + h) * (size_t)LV * LA;
        float a0 = 0.f, a1 = 0.f, a2 = 0.f, a3 = 0.f;
        #pragma unroll 1
        for (int r = 0; r < NCV; r += 4) {
            float m0 = Mb[s_off[r + 0] + tid];
            float m1 = Mb[s_off[r + 1] + tid];
            float m2 = Mb[s_off[r + 2] + tid];
            float m3 = Mb[s_off[r + 3] + tid];
            a0 = fmaf(m0, s_w[r + 0], a0);
            a1 = fmaf(m1, s_w[r + 1], a1);
            a2 = fmaf(m2, s_w[r + 2], a2);
            a3 = fmaf(m3, s_w[r + 3], a3);
        }
        g_posa[(size_t)(n * H + h) * LA + tid] = (a0 + a1) + (a2 + a3);
    }
}

// ---------- kernel 3: spu dot + sigmoid + cls ----------
// grid (H, NB, 2): z==0 -> v side, z==1 -> a side
__global__ void __launch_bounds__(512, 2)
kspu(const float* __restrict__ pos_v_q, const float* __restrict__ pos_v_k,
     const float* __restrict__ pos_a_q, const float* __restrict__ pos_a_k,
     const float* __restrict__ spu_a_cls, const float* __restrict__ spu_v_cls,
     float* __restrict__ out) {
    int h = blockIdx.x, n = blockIdx.y, side = blockIdx.z;
    int tid = threadIdx.x;

    __shared__ int   s_idxL[NCV];
    __shared__ float s_wL[NCV];
    __shared__ float s_cls[DH];
    __shared__ float s_red[512];

    int Lcnt, Lfull, clsoff;
    const float *kten, *qten, *cls, *posbuf;
    const int *cidxL; const float *gwL;
    float invS_pos, invS_cls;
    float* acc;
    if (side == 0) {
        Lcnt = NCV; Lfull = LV; clsoff = OFF_VCLS;
        kten = pos_v_k; qten = pos_v_q; cls = spu_a_cls;
        cidxL = g_cidx_v; gwL = g_w_v;
        posbuf = g_posv + (size_t)(n * H + h) * LV;
        invS_pos = g_invS_va[n]; invS_cls = g_invS_av[n];
        acc = g_probv + n * NCV;
    } else {
        Lcnt = NCA; Lfull = LA; clsoff = OFF_ACLS;
        kten = pos_a_k; qten = pos_a_q; cls = spu_v_cls;
        cidxL = g_cidx_a; gwL = g_w_a;
        posbuf = g_posa + (size_t)(n * H + h) * LA;
        invS_pos = g_invS_av[n]; invS_cls = g_invS_va[n];
        acc = g_proba + n * NCA;
    }

    if (tid < Lcnt) {
        s_idxL[tid] = cidxL[n * Lcnt + tid];
        s_wL[tid]   = gwL[n * Lcnt + tid];
    }
    if (tid < DH) s_cls[tid] = cls[(n * H + h) * DH + tid];
    __syncthreads();

    const float* kbase = kten + (size_t)(n * H + h) * Lfull * DH;
    if (tid < Lcnt) {
        int il = s_idxL[tid];
        const float4* krow = (const float4*)(kbase + (size_t)il * DH);
        float spu = 0.f;
        #pragma unroll
        for (int d4 = 0; d4 < DH / 4; d4++) {
            float4 v = krow[d4];
            spu = fmaf(v.x, s_cls[4 * d4 + 0], spu);
            spu = fmaf(v.y, s_cls[4 * d4 + 1], spu);
            spu = fmaf(v.z, s_cls[4 * d4 + 2], spu);
            spu = fmaf(v.w, s_cls[4 * d4 + 3], spu);
        }
        spu *= 0.125f;
        float posv = posbuf[il] * invS_pos;
        float sig = 1.f / (1.f + __expf(posv - spu));
        atomicAdd(&acc[tid], sig);
    }

    // cls: weighted sum of gathered q rows -> 64 floats, direct store
    const float* qbase = qten + (size_t)(n * H + h) * Lfull * DH;
    {
        int g = tid >> 6, d = tid & 63;
        float a2 = 0.f;
        for (int l = g; l < Lcnt; l += 8)
            a2 = fmaf(qbase[(size_t)s_idxL[l] * DH + d], s_wL[l], a2);
        s_red[tid] = a2;
        __syncthreads();
        if (tid < DH) {
            float t = 0.f;
            #pragma unroll
            for (int gg = 0; gg < 8; gg++) t += s_red[gg * 64 + tid];
            out[(size_t)n * ROW + clsoff + h * DH + tid] = t * invS_cls;
        }
    }
}

// ---------- kernel 4: defaults + scatter + prune ----------
__global__ void kfin(const float* __restrict__ n_attn_av,
                     const float* __restrict__ n_attn_va,
                     const float* __restrict__ u_v,
                     const float* __restrict__ u_a,
                     float* __restrict__ out) {
    int n = blockIdx.x, tid = threadIdx.x;
    float* row = out + (size_t)n * ROW;
    for (int j = tid; j < LV; j += blockDim.x) {
        row[OFF_PROBV + j] = 0.f;
        row[OFF_PRAV + j]  = n_attn_av[n * LV + j];
    }
    for (int j = tid; j < LA; j += blockDim.x) {
        row[OFF_PROBA + j] = 0.f;
        row[OFF_PRVA + j]  = n_attn_va[n * LA + j];
    }
    __syncthreads();
    if (tid < NCV) {
        int pos = g_cidx_v[n * NCV + tid];
        float p = g_probv[n * NCV + tid] * (1.f / 12.f);
        row[OFF_PROBV + pos] = p;
        row[OFF_PRAV + pos]  = (u_v[n * LV + pos] < p) ? 0.f : n_attn_av[n * LV + pos];
    }
    if (tid < NCA) {
        int pos = g_cidx_a[n * NCA + tid];
        float p = g_proba[n * NCA + tid] * (1.f / 12.f);
        row[OFF_PROBA + pos] = p;
        row[OFF_PRVA + pos]  = (u_a[n * LA + pos] < p) ? 0.f : n_attn_va[n * LA + pos];
    }
}

extern "C" void kernel_launch(void* const* d_in, const int* in_sizes, int n_in,
                              void* d_out, int out_size) {
    const float* pos_v_q   = (const float*)d_in[0];
    const float* pos_v_k   = (const float*)d_in[1];
    const float* pos_a_q   = (const float*)d_in[2];
    const float* pos_a_k   = (const float*)d_in[3];
    const float* M_av      = (const float*)d_in[4];
    const float* M_va      = (const float*)d_in[5];
    const float* n_attn_av = (const float*)d_in[6];
    const float* n_attn_va = (const float*)d_in[7];
    const float* spu_a_cls = (const float*)d_in[8];
    const float* spu_v_cls = (const float*)d_in[9];
    const float* u_v       = (const float*)d_in[10];
    const float* u_a       = (const float*)d_in[11];
    const int*   ids_v     = (const int*)d_in[12];
    const int*   ids_a     = (const int*)d_in[13];
    float* out = (float*)d_out;

    kprep<<<dim3(NB, 2), 512>>>(n_attn_av, n_attn_va, ids_v, ids_a);
    kpos<<<dim3(H, NB, 3), 512>>>(M_av, M_va);
    kspu<<<dim3(H, NB, 2), 512>>>(pos_v_q, pos_v_k, pos_a_q, pos_a_k,
                                  spu_a_cls, spu_v_cls, out);
    kfin<<<NB, 512>>>(n_attn_av, n_attn_va, u_v, u_a, out);
}

// round 9
// speedup vs baseline: 1.4341x; 1.4341x over previous
#include <cuda_runtime.h>
#include <math.h>

#define NB  8
#define H   12
#define DH  64
#define LV  1568
#define LA  512
#define NCV 392
#define NCA 256
#define ROW 5696
#define OFF_PROBV 0
#define OFF_PROBA 1568
#define OFF_VCLS  2080
#define OFF_ACLS  2848
#define OFF_PRAV  3616
#define OFF_PRVA  5184

// ---------- scratch ----------
__device__ int   g_cidx_v[NB * NCV];   // sorted gathered v-token ids
__device__ float g_w_v[NB * NCV];
__device__ int   g_cidx_a[NB * NCA];
__device__ float g_w_a[NB * NCA];
__device__ float g_invS_av[NB];
__device__ float g_invS_va[NB];
__device__ float g_probv[NB * NCV];
__device__ float g_proba[NB * NCA];

// ---------- kernel 1: sorted gather via inverse permutation + block scan ----------
// grid (NB, 2): side 0 = v, side 1 = a
__global__ void kprep(const float* __restrict__ n_attn_av,
                      const float* __restrict__ n_attn_va,
                      const int* __restrict__ ids_v,
                      const int* __restrict__ ids_a) {
    int n = blockIdx.x, side = blockIdx.y, tid = threadIdx.x;
    int lane = tid & 31, wrp = tid >> 5;
    __shared__ int   s_rank[LV];
    __shared__ int   s_wsum[16];
    __shared__ float s_red[512];

    int full = side ? LA : LV;
    int cnt  = side ? NCA : NCV;
    const int*   ids = side ? ids_a : ids_v;
    const float* na  = side ? n_attn_va : n_attn_av;

    for (int t = tid; t < full; t += 512) s_rank[ids[n * full + t]] = t;
    if (side) { if (tid < NCA) g_proba[n * NCA + tid] = 0.f; }
    else      { if (tid < NCV) g_probv[n * NCV + tid] = 0.f; }
    __syncthreads();

    // token j kept iff rank < cnt; ascending j == sorted order
    int per = (full + 511) >> 9;
    int base = tid * per;
    int keep[4]; int k = 0; float ws = 0.f;
    for (int i = 0; i < per; i++) {
        int j = base + i;
        if (j < full && s_rank[j] < cnt) { keep[k++] = j; ws += na[n * full + j]; }
    }
    int inc = k;
    for (int d = 1; d < 32; d <<= 1) {
        int v = __shfl_up_sync(0xffffffffu, inc, d);
        if (lane >= d) inc += v;
    }
    if (lane == 31) s_wsum[wrp] = inc;
    __syncthreads();
    if (wrp == 0 && lane < 16) {
        int v = s_wsum[lane];
        for (int d = 1; d < 16; d <<= 1) {
            int u = __shfl_up_sync(0xffffu, v, d);
            if (lane >= d) v += u;
        }
        s_wsum[lane] = v;
    }
    __syncthreads();
    int off = (wrp ? s_wsum[wrp - 1] : 0) + inc - k;
    for (int i = 0; i < k; i++) {
        int j = keep[i];
        int slot = off + i;
        if (side) { g_cidx_a[n * NCA + slot] = j; g_w_a[n * NCA + slot] = na[n * LA + j]; }
        else      { g_cidx_v[n * NCV + slot] = j; g_w_v[n * NCV + slot] = na[n * LV + j]; }
    }
    s_red[tid] = ws;
    __syncthreads();
    for (int s = 256; s > 0; s >>= 1) {
        if (tid < s) s_red[tid] += s_red[tid + s];
        __syncthreads();
    }
    if (tid == 0) {
        if (side) g_invS_va[n] = 1.f / s_red[0];
        else      g_invS_av[n] = 1.f / s_red[0];
    }
}

// ---------- kernel 2: round-7 structure, 8-way MLP unroll in the pos loop ----------
// grid (H, NB, 2): z==0 -> v side, z==1 -> a side
__global__ void __launch_bounds__(512, 2)
kmain(const float* __restrict__ pos_v_q, const float* __restrict__ pos_v_k,
      const float* __restrict__ pos_a_q, const float* __restrict__ pos_a_k,
      const float* __restrict__ M_av,    const float* __restrict__ M_va,
      const float* __restrict__ spu_a_cls, const float* __restrict__ spu_v_cls,
      float* __restrict__ out) {
    int h = blockIdx.x, n = blockIdx.y, side = blockIdx.z;
    int tid = threadIdx.x;

    __shared__ int   s_idxL[NCV];
    __shared__ float s_wL[NCV];
    __shared__ int   s_offS[NCV];
    __shared__ float s_wS[NCV];
    __shared__ float s_cls[DH];
    __shared__ float s_red[512];

    int Lcnt, Scnt, Mstride, clsoff;
    const float *kten, *qten, *M, *cls;
    const int *cidxL, *cidxS;
    const float *gwL, *gwS;
    float invS_pos, invS_cls;
    float* acc;
    if (side == 0) {
        Lcnt = NCV; Scnt = NCA; Mstride = LV; clsoff = OFF_VCLS;
        kten = pos_v_k; qten = pos_v_q; M = M_av; cls = spu_a_cls;
        cidxL = g_cidx_v; cidxS = g_cidx_a;
        gwL = g_w_v; gwS = g_w_a;
        invS_pos = g_invS_va[n]; invS_cls = g_invS_av[n];
        acc = g_probv + n * NCV;
    } else {
        Lcnt = NCA; Scnt = NCV; Mstride = LA; clsoff = OFF_ACLS;
        kten = pos_a_k; qten = pos_a_q; M = M_va; cls = spu_v_cls;
        cidxL = g_cidx_a; cidxS = g_cidx_v;
        gwL = g_w_a; gwS = g_w_v;
        invS_pos = g_invS_av[n]; invS_cls = g_invS_va[n];
        acc = g_proba + n * NCA;
    }

    if (tid < Lcnt) {
        s_idxL[tid] = cidxL[n * Lcnt + tid];
        s_wL[tid]   = gwL[n * Lcnt + tid];
    }
    if (tid < Scnt) {
        s_offS[tid] = cidxS[n * Scnt + tid] * Mstride;
        s_wS[tid]   = gwS[n * Scnt + tid];
    }
    if (tid < DH) s_cls[tid] = cls[(n * H + h) * DH + tid];
    __syncthreads();

    const float* kbase = kten + (size_t)(n * H + h) * (side ? LA : LV) * DH;
    const float* Mbase = M + (size_t)(n * H + h) * (size_t)LA * LV;

    if (tid < Lcnt) {
        int il = s_idxL[tid];
        const float4* krow = (const float4*)(kbase + (size_t)il * DH);
        float spu = 0.f;
        #pragma unroll
        for (int d4 = 0; d4 < DH / 4; d4++) {
            float4 v = krow[d4];
            spu = fmaf(v.x, s_cls[4 * d4 + 0], spu);
            spu = fmaf(v.y, s_cls[4 * d4 + 1], spu);
            spu = fmaf(v.z, s_cls[4 * d4 + 2], spu);
            spu = fmaf(v.w, s_cls[4 * d4 + 3], spu);
        }
        spu *= 0.125f;
        // pos: 8-way unroll -> 8 outstanding LDGs per thread
        float p0 = 0.f, p1 = 0.f, p2 = 0.f, p3 = 0.f;
        float p4 = 0.f, p5 = 0.f, p6 = 0.f, p7 = 0.f;
        #pragma unroll 1
        for (int a = 0; a < Scnt; a += 8) {
            float m0 = Mbase[s_offS[a + 0] + il];
            float m1 = Mbase[s_offS[a + 1] + il];
            float m2 = Mbase[s_offS[a + 2] + il];
            float m3 = Mbase[s_offS[a + 3] + il];
            float m4 = Mbase[s_offS[a + 4] + il];
            float m5 = Mbase[s_offS[a + 5] + il];
            float m6 = Mbase[s_offS[a + 6] + il];
            float m7 = Mbase[s_offS[a + 7] + il];
            p0 = fmaf(m0, s_wS[a + 0], p0);
            p1 = fmaf(m1, s_wS[a + 1], p1);
            p2 = fmaf(m2, s_wS[a + 2], p2);
            p3 = fmaf(m3, s_wS[a + 3], p3);
            p4 = fmaf(m4, s_wS[a + 4], p4);
            p5 = fmaf(m5, s_wS[a + 5], p5);
            p6 = fmaf(m6, s_wS[a + 6], p6);
            p7 = fmaf(m7, s_wS[a + 7], p7);
        }
        float posv = (((p0 + p1) + (p2 + p3)) + ((p4 + p5) + (p6 + p7))) * invS_pos;
        float sig = 1.f / (1.f + __expf(posv - spu));
        atomicAdd(&acc[tid], sig);
    }

    // cls: weighted sum of gathered q rows -> 64 floats, direct store
    const float* qbase = qten + (size_t)(n * H + h) * (side ? LA : LV) * DH;
    {
        int g = tid >> 6, d = tid & 63;
        float a2 = 0.f;
        for (int l = g; l < Lcnt; l += 8)
            a2 = fmaf(qbase[(size_t)s_idxL[l] * DH + d], s_wL[l], a2);
        s_red[tid] = a2;
        __syncthreads();
        if (tid < DH) {
            float t = 0.f;
            #pragma unroll
            for (int gg = 0; gg < 8; gg++) t += s_red[gg * 64 + tid];
            out[(size_t)n * ROW + clsoff + h * DH + tid] = t * invS_cls;
        }
    }
}

// ---------- kernel 3: defaults + scatter + prune; grid (NB, 2) ----------
__global__ void kfin(const float* __restrict__ n_attn_av,
                     const float* __restrict__ n_attn_va,
                     const float* __restrict__ u_v,
                     const float* __restrict__ u_a,
                     float* __restrict__ out) {
    int n = blockIdx.x, side = blockIdx.y, tid = threadIdx.x;
    float* row = out + (size_t)n * ROW;
    if (side == 0) {
        for (int j = tid; j < LV; j += 512) {
            row[OFF_PROBV + j] = 0.f;
            row[OFF_PRAV + j]  = n_attn_av[n * LV + j];
        }
        __syncthreads();
        if (tid < NCV) {
            int pos = g_cidx_v[n * NCV + tid];
            float p = g_probv[n * NCV + tid] * (1.f / 12.f);
            row[OFF_PROBV + pos] = p;
            row[OFF_PRAV + pos]  = (u_v[n * LV + pos] < p) ? 0.f : n_attn_av[n * LV + pos];
        }
    } else {
        for (int j = tid; j < LA; j += 512) {
            row[OFF_PROBA + j] = 0.f;
            row[OFF_PRVA + j]  = n_attn_va[n * LA + j];
        }
        __syncthreads();
        if (tid < NCA) {
            int pos = g_cidx_a[n * NCA + tid];
            float p = g_proba[n * NCA + tid] * (1.f / 12.f);
            row[OFF_PROBA + pos] = p;
            row[OFF_PRVA + pos]  = (u_a[n * LA + pos] < p) ? 0.f : n_attn_va[n * LA + pos];
        }
    }
}

extern "C" void kernel_launch(void* const* d_in, const int* in_sizes, int n_in,
                              void* d_out, int out_size) {
    const float* pos_v_q   = (const float*)d_in[0];
    const float* pos_v_k   = (const float*)d_in[1];
    const float* pos_a_q   = (const float*)d_in[2];
    const float* pos_a_k   = (const float*)d_in[3];
    const float* M_av      = (const float*)d_in[4];
    const float* M_va      = (const float*)d_in[5];
    const float* n_attn_av = (const float*)d_in[6];
    const float* n_attn_va = (const float*)d_in[7];
    const float* spu_a_cls = (const float*)d_in[8];
    const float* spu_v_cls = (const float*)d_in[9];
    const float* u_v       = (const float*)d_in[10];
    const float* u_a       = (const float*)d_in[11];
    const int*   ids_v     = (const int*)d_in[12];
    const int*   ids_a     = (const int*)d_in[13];
    float* out = (float*)d_out;

    kprep<<<dim3(NB, 2), 512>>>(n_attn_av, n_attn_va, ids_v, ids_a);
    kmain<<<dim3(H, NB, 2), 512>>>(pos_v_q, pos_v_k, pos_a_q, pos_a_k,
                                   M_av, M_va, spu_a_cls, spu_v_cls, out);
    kfin<<<dim3(NB, 2), 512>>>(n_attn_av, n_attn_va, u_v, u_a, out);
}

// round 10
// speedup vs baseline: 1.6372x; 1.1416x over previous
#include <cuda_runtime.h>
#include <math.h>

#define NB  8
#define H   12
#define DH  64
#define LV  1568
#define LA  512
#define NCV 392
#define NCA 256
#define ROW 5696
#define OFF_PROBV 0
#define OFF_PROBA 1568
#define OFF_VCLS  2080
#define OFF_ACLS  2848
#define OFF_PRAV  3616
#define OFF_PRVA  5184

// ---------- scratch ----------
__device__ int   g_cidx_v[NB * NCV];   // sorted gathered v-token ids
__device__ float g_w_v[NB * NCV];
__device__ int   g_cidx_a[NB * NCA];
__device__ float g_w_a[NB * NCA];
__device__ float g_invS_av[NB];
__device__ float g_invS_va[NB];
__device__ float g_probv[NB * NCV];
__device__ float g_proba[NB * NCA];

// ---------- kernel 1: compaction (sides 0/1) + output default fill (sides 2/3) ----------
// grid (NB, 4)
__global__ void kprep(const float* __restrict__ n_attn_av,
                      const float* __restrict__ n_attn_va,
                      const int* __restrict__ ids_v,
                      const int* __restrict__ ids_a,
                      float* __restrict__ out) {
    int n = blockIdx.x, side = blockIdx.y, tid = threadIdx.x;

    if (side >= 2) {
        // default fill: prob = 0, prune = n_attn (scatter in kfin overwrites kept slots)
        float* row = out + (size_t)n * ROW;
        if (side == 2) {
            for (int j = tid; j < LV; j += 512) {
                row[OFF_PROBV + j] = 0.f;
                row[OFF_PRAV + j]  = n_attn_av[n * LV + j];
            }
        } else {
            for (int j = tid; j < LA; j += 512) {
                row[OFF_PROBA + j] = 0.f;
                row[OFF_PRVA + j]  = n_attn_va[n * LA + j];
            }
        }
        return;
    }

    int lane = tid & 31, wrp = tid >> 5;
    __shared__ int   s_rank[LV];
    __shared__ int   s_wsum[16];
    __shared__ float s_red[512];

    int full = side ? LA : LV;
    int cnt  = side ? NCA : NCV;
    const int*   ids = side ? ids_a : ids_v;
    const float* na  = side ? n_attn_va : n_attn_av;

    for (int t = tid; t < full; t += 512) s_rank[ids[n * full + t]] = t;
    if (side) { if (tid < NCA) g_proba[n * NCA + tid] = 0.f; }
    else      { if (tid < NCV) g_probv[n * NCV + tid] = 0.f; }
    __syncthreads();

    // token j kept iff rank < cnt; ascending j == sorted order
    int per = (full + 511) >> 9;
    int base = tid * per;
    int keep[4]; int k = 0; float ws = 0.f;
    for (int i = 0; i < per; i++) {
        int j = base + i;
        if (j < full && s_rank[j] < cnt) { keep[k++] = j; ws += na[n * full + j]; }
    }
    int inc = k;
    for (int d = 1; d < 32; d <<= 1) {
        int v = __shfl_up_sync(0xffffffffu, inc, d);
        if (lane >= d) inc += v;
    }
    if (lane == 31) s_wsum[wrp] = inc;
    __syncthreads();
    if (wrp == 0 && lane < 16) {
        int v = s_wsum[lane];
        for (int d = 1; d < 16; d <<= 1) {
            int u = __shfl_up_sync(0xffffu, v, d);
            if (lane >= d) v += u;
        }
        s_wsum[lane] = v;
    }
    __syncthreads();
    int off = (wrp ? s_wsum[wrp - 1] : 0) + inc - k;
    for (int i = 0; i < k; i++) {
        int j = keep[i];
        int slot = off + i;
        if (side) { g_cidx_a[n * NCA + slot] = j; g_w_a[n * NCA + slot] = na[n * LA + j]; }
        else      { g_cidx_v[n * NCV + slot] = j; g_w_v[n * NCV + slot] = na[n * LV + j]; }
    }
    s_red[tid] = ws;
    __syncthreads();
    for (int s = 256; s > 0; s >>= 1) {
        if (tid < s) s_red[tid] += s_red[tid + s];
        __syncthreads();
    }
    if (tid == 0) {
        if (side) g_invS_va[n] = 1.f / s_red[0];
        else      g_invS_av[n] = 1.f / s_red[0];
    }
}

// ---------- kernel 2: EXACT round-7 kmain (4-way pos loop) ----------
// grid (H, NB, 2): z==0 -> v side, z==1 -> a side
__global__ void __launch_bounds__(512, 2)
kmain(const float* __restrict__ pos_v_q, const float* __restrict__ pos_v_k,
      const float* __restrict__ pos_a_q, const float* __restrict__ pos_a_k,
      const float* __restrict__ M_av,    const float* __restrict__ M_va,
      const float* __restrict__ spu_a_cls, const float* __restrict__ spu_v_cls,
      float* __restrict__ out) {
    int h = blockIdx.x, n = blockIdx.y, side = blockIdx.z;
    int tid = threadIdx.x;

    __shared__ int   s_idxL[NCV];
    __shared__ float s_wL[NCV];
    __shared__ int   s_offS[NCV];
    __shared__ float s_wS[NCV];
    __shared__ float s_cls[DH];
    __shared__ float s_red[512];

    int Lcnt, Scnt, Mstride, clsoff;
    const float *kten, *qten, *M, *cls;
    const int *cidxL, *cidxS;
    const float *gwL, *gwS;
    float invS_pos, invS_cls;
    float* acc;
    if (side == 0) {
        Lcnt = NCV; Scnt = NCA; Mstride = LV; clsoff = OFF_VCLS;
        kten = pos_v_k; qten = pos_v_q; M = M_av; cls = spu_a_cls;
        cidxL = g_cidx_v; cidxS = g_cidx_a;
        gwL = g_w_v; gwS = g_w_a;
        invS_pos = g_invS_va[n]; invS_cls = g_invS_av[n];
        acc = g_probv + n * NCV;
    } else {
        Lcnt = NCA; Scnt = NCV; Mstride = LA; clsoff = OFF_ACLS;
        kten = pos_a_k; qten = pos_a_q; M = M_va; cls = spu_v_cls;
        cidxL = g_cidx_a; cidxS = g_cidx_v;
        gwL = g_w_a; gwS = g_w_v;
        invS_pos = g_invS_av[n]; invS_cls = g_invS_va[n];
        acc = g_proba + n * NCA;
    }

    if (tid < Lcnt) {
        s_idxL[tid] = cidxL[n * Lcnt + tid];
        s_wL[tid]   = gwL[n * Lcnt + tid];
    }
    if (tid < Scnt) {
        s_offS[tid] = cidxS[n * Scnt + tid] * Mstride;
        s_wS[tid]   = gwS[n * Scnt + tid];
    }
    if (tid < DH) s_cls[tid] = cls[(n * H + h) * DH + tid];
    __syncthreads();

    const float* kbase = kten + (size_t)(n * H + h) * (side ? LA : LV) * DH;
    const float* Mbase = M + (size_t)(n * H + h) * (size_t)LA * LV;

    if (tid < Lcnt) {
        int il = s_idxL[tid];
        const float4* krow = (const float4*)(kbase + (size_t)il * DH);
        float spu = 0.f;
        #pragma unroll
        for (int d4 = 0; d4 < DH / 4; d4++) {
            float4 v = krow[d4];
            spu = fmaf(v.x, s_cls[4 * d4 + 0], spu);
            spu = fmaf(v.y, s_cls[4 * d4 + 1], spu);
            spu = fmaf(v.z, s_cls[4 * d4 + 2], spu);
            spu = fmaf(v.w, s_cls[4 * d4 + 3], spu);
        }
        spu *= 0.125f;
        float p0 = 0.f, p1 = 0.f, p2 = 0.f, p3 = 0.f;
        for (int a = 0; a < Scnt; a += 4) {
            p0 = fmaf(Mbase[s_offS[a + 0] + il], s_wS[a + 0], p0);
            p1 = fmaf(Mbase[s_offS[a + 1] + il], s_wS[a + 1], p1);
            p2 = fmaf(Mbase[s_offS[a + 2] + il], s_wS[a + 2], p2);
            p3 = fmaf(Mbase[s_offS[a + 3] + il], s_wS[a + 3], p3);
        }
        float posv = ((p0 + p1) + (p2 + p3)) * invS_pos;
        float sig = 1.f / (1.f + __expf(posv - spu));
        atomicAdd(&acc[tid], sig);
    }

    // cls: weighted sum of gathered q rows -> 64 floats, direct store
    const float* qbase = qten + (size_t)(n * H + h) * (side ? LA : LV) * DH;
    {
        int g = tid >> 6, d = tid & 63;
        float a2 = 0.f;
        for (int l = g; l < Lcnt; l += 8)
            a2 = fmaf(qbase[(size_t)s_idxL[l] * DH + d], s_wL[l], a2);
        s_red[tid] = a2;
        __syncthreads();
        if (tid < DH) {
            float t = 0.f;
            #pragma unroll
            for (int gg = 0; gg < 8; gg++) t += s_red[gg * 64 + tid];
            out[(size_t)n * ROW + clsoff + h * DH + tid] = t * invS_cls;
        }
    }
}

// ---------- kernel 3: scatter + prune only (defaults already written by kprep) ----------
// grid (NB, 2)
__global__ void kfin(const float* __restrict__ n_attn_av,
                     const float* __restrict__ n_attn_va,
                     const float* __restrict__ u_v,
                     const float* __restrict__ u_a,
                     float* __restrict__ out) {
    int n = blockIdx.x, side = blockIdx.y, tid = threadIdx.x;
    float* row = out + (size_t)n * ROW;
    if (side == 0) {
        if (tid < NCV) {
            int pos = g_cidx_v[n * NCV + tid];
            float p = g_probv[n * NCV + tid] * (1.f / 12.f);
            row[OFF_PROBV + pos] = p;
            row[OFF_PRAV + pos]  = (u_v[n * LV + pos] < p) ? 0.f : n_attn_av[n * LV + pos];
        }
    } else {
        if (tid < NCA) {
            int pos = g_cidx_a[n * NCA + tid];
            float p = g_proba[n * NCA + tid] * (1.f / 12.f);
            row[OFF_PROBA + pos] = p;
            row[OFF_PRVA + pos]  = (u_a[n * LA + pos] < p) ? 0.f : n_attn_va[n * LA + pos];
        }
    }
}

extern "C" void kernel_launch(void* const* d_in, const int* in_sizes, int n_in,
                              void* d_out, int out_size) {
    const float* pos_v_q   = (const float*)d_in[0];
    const float* pos_v_k   = (const float*)d_in[1];
    const float* pos_a_q   = (const float*)d_in[2];
    const float* pos_a_k   = (const float*)d_in[3];
    const float* M_av      = (const float*)d_in[4];
    const float* M_va      = (const float*)d_in[5];
    const float* n_attn_av = (const float*)d_in[6];
    const float* n_attn_va = (const float*)d_in[7];
    const float* spu_a_cls = (const float*)d_in[8];
    const float* spu_v_cls = (const float*)d_in[9];
    const float* u_v       = (const float*)d_in[10];
    const float* u_a       = (const float*)d_in[11];
    const int*   ids_v     = (const int*)d_in[12];
    const int*   ids_a     = (const int*)d_in[13];
    float* out = (float*)d_out;

    kprep<<<dim3(NB, 4), 512>>>(n_attn_av, n_attn_va, ids_v, ids_a, out);
    kmain<<<dim3(H, NB, 2), 512>>>(pos_v_q, pos_v_k, pos_a_q, pos_a_k,
                                   M_av, M_va, spu_a_cls, spu_v_cls, out);
    kfin<<<dim3(NB, 2), 512>>>(n_attn_av, n_attn_va, u_v, u_a, out);
}